// round 1
// baseline (speedup 1.0000x reference)
#include <cuda_runtime.h>
#include <cuda_bf16.h>

// Problem constants (fixed shapes from reference)
#define T_TOK 32768
#define H_DIM 2048
#define I_DIM 768

// Scratch for intermediate activation x = silu(gate)*up : [T, I] fp32 (96 MB)
__device__ float g_x[(size_t)T_TOK * I_DIM];

// ---------------------------------------------------------------------------
// Kernel 1: gate_up GEMM fused with SiLU*Mul.
//   A = hidden_states [T, H] row-major
//   W = w_gate_up     [H, 2I] row-major (cols [0:I]=gate, [I:2I]=up)
//   X = g_x           [T, I]
// Tiling: BM=128, BN=64, BK=16. 256 threads, per-thread microtile 8(M)x4(N),
// with BOTH gate and up accumulators (A tile shared between the two B tiles).
// ---------------------------------------------------------------------------
__global__ __launch_bounds__(256, 2)
void gateup_silu_kernel(const float* __restrict__ A,
                        const float* __restrict__ W,
                        float* __restrict__ X)
{
    constexpr int BM = 128, BN = 64, BK = 16;
    constexpr int AP = 130;  // pad to kill store bank conflicts ((k*130)%32 spreads)

    __shared__ float As[BK][AP];   // transposed A tile: As[k][m]
    __shared__ float Bg[BK][BN];   // gate weights tile
    __shared__ float Bu[BK][BN];   // up weights tile

    const int bm = blockIdx.y * BM;
    const int bn = blockIdx.x * BN;
    const int tid = threadIdx.x;
    const int tx = tid & 15;   // N dim: 16 threads
    const int ty = tid >> 4;   // M dim: 16 threads

    float accg[8][4];
    float accu[8][4];
#pragma unroll
    for (int i = 0; i < 8; i++)
#pragma unroll
        for (int j = 0; j < 4; j++) { accg[i][j] = 0.f; accu[i][j] = 0.f; }

    for (int k0 = 0; k0 < H_DIM; k0 += BK) {
        // --- load A tile [BM x BK] as float4, store transposed ---
#pragma unroll
        for (int l = 0; l < 2; l++) {
            int f   = tid + l * 256;      // 0..511
            int row = f >> 2;             // 0..127
            int c4  = f & 3;              // 0..3 (which float4 in the row)
            float4 v = *reinterpret_cast<const float4*>(
                &A[(size_t)(bm + row) * H_DIM + k0 + c4 * 4]);
            As[c4 * 4 + 0][row] = v.x;
            As[c4 * 4 + 1][row] = v.y;
            As[c4 * 4 + 2][row] = v.z;
            As[c4 * 4 + 3][row] = v.w;
        }
        // --- load B tiles [BK x BN] for gate and up ---
        {
            int row = tid >> 4;  // 0..15 (k)
            int c4  = tid & 15;  // 0..15 (float4 within 64-wide row)
            const float* wrow = &W[(size_t)(k0 + row) * (2 * I_DIM)];
            float4 vg = *reinterpret_cast<const float4*>(&wrow[bn + c4 * 4]);
            float4 vu = *reinterpret_cast<const float4*>(&wrow[I_DIM + bn + c4 * 4]);
            *reinterpret_cast<float4*>(&Bg[row][c4 * 4]) = vg;
            *reinterpret_cast<float4*>(&Bu[row][c4 * 4]) = vu;
        }
        __syncthreads();

#pragma unroll
        for (int k = 0; k < BK; k++) {
            float a[8];
#pragma unroll
            for (int i = 0; i < 8; i++) a[i] = As[k][ty * 8 + i];
            float4 bg4 = *reinterpret_cast<float4*>(&Bg[k][tx * 4]);
            float4 bu4 = *reinterpret_cast<float4*>(&Bu[k][tx * 4]);
            float bg[4] = {bg4.x, bg4.y, bg4.z, bg4.w};
            float bu[4] = {bu4.x, bu4.y, bu4.z, bu4.w};
#pragma unroll
            for (int i = 0; i < 8; i++) {
#pragma unroll
                for (int j = 0; j < 4; j++) {
                    accg[i][j] = fmaf(a[i], bg[j], accg[i][j]);
                    accu[i][j] = fmaf(a[i], bu[j], accu[i][j]);
                }
            }
        }
        __syncthreads();
    }

    // --- epilogue: silu(gate) * up ---
#pragma unroll
    for (int i = 0; i < 8; i++) {
        int trow = bm + ty * 8 + i;
        float* xrow = &X[(size_t)trow * I_DIM + bn + tx * 4];
#pragma unroll
        for (int j = 0; j < 4; j++) {
            float g = accg[i][j];
            float u = accu[i][j];
            float sig = 1.0f / (1.0f + __expf(-g));
            xrow[j] = g * sig * u;
        }
    }
}

// ---------------------------------------------------------------------------
// Kernel 2: down projection GEMM.
//   X  = g_x    [T, I] row-major
//   Wd = w_down [I, H] row-major
//   O  = out    [T, H]
// Tiling: BM=128, BN=128, BK=16. 256 threads, per-thread microtile 8x8.
// ---------------------------------------------------------------------------
__global__ __launch_bounds__(256, 2)
void down_kernel(const float* __restrict__ X,
                 const float* __restrict__ Wd,
                 float* __restrict__ O)
{
    constexpr int BM = 128, BN = 128, BK = 16;
    constexpr int AP = 130;

    __shared__ float As[BK][AP];   // transposed X tile: As[k][m]
    __shared__ float Bs[BK][BN];   // Wd tile

    const int bm = blockIdx.y * BM;
    const int bn = blockIdx.x * BN;
    const int tid = threadIdx.x;
    const int tx = tid & 15;   // N
    const int ty = tid >> 4;   // M

    float acc[8][8];
#pragma unroll
    for (int i = 0; i < 8; i++)
#pragma unroll
        for (int j = 0; j < 8; j++) acc[i][j] = 0.f;

    for (int k0 = 0; k0 < I_DIM; k0 += BK) {
        // A tile [BM x BK] -> transposed
#pragma unroll
        for (int l = 0; l < 2; l++) {
            int f   = tid + l * 256;
            int row = f >> 2;
            int c4  = f & 3;
            float4 v = *reinterpret_cast<const float4*>(
                &X[(size_t)(bm + row) * I_DIM + k0 + c4 * 4]);
            As[c4 * 4 + 0][row] = v.x;
            As[c4 * 4 + 1][row] = v.y;
            As[c4 * 4 + 2][row] = v.z;
            As[c4 * 4 + 3][row] = v.w;
        }
        // B tile [BK x BN]: 512 float4, 2 per thread
#pragma unroll
        for (int l = 0; l < 2; l++) {
            int f   = tid + l * 256;   // 0..511
            int row = f >> 5;          // 0..15
            int c4  = f & 31;          // 0..31
            float4 v = *reinterpret_cast<const float4*>(
                &Wd[(size_t)(k0 + row) * H_DIM + bn + c4 * 4]);
            *reinterpret_cast<float4*>(&Bs[row][c4 * 4]) = v;
        }
        __syncthreads();

#pragma unroll
        for (int k = 0; k < BK; k++) {
            float a[8];
#pragma unroll
            for (int i = 0; i < 8; i++) a[i] = As[k][ty * 8 + i];
            float4 b0 = *reinterpret_cast<float4*>(&Bs[k][tx * 8]);
            float4 b1 = *reinterpret_cast<float4*>(&Bs[k][tx * 8 + 4]);
            float b[8] = {b0.x, b0.y, b0.z, b0.w, b1.x, b1.y, b1.z, b1.w};
#pragma unroll
            for (int i = 0; i < 8; i++)
#pragma unroll
                for (int j = 0; j < 8; j++)
                    acc[i][j] = fmaf(a[i], b[j], acc[i][j]);
        }
        __syncthreads();
    }

#pragma unroll
    for (int i = 0; i < 8; i++) {
        int trow = bm + ty * 8 + i;
        float* orow = &O[(size_t)trow * H_DIM + bn + tx * 8];
#pragma unroll
        for (int j = 0; j < 8; j++) orow[j] = acc[i][j];
    }
}

extern "C" void kernel_launch(void* const* d_in, const int* in_sizes, int n_in,
                              void* d_out, int out_size)
{
    const float* hidden   = (const float*)d_in[0];  // [T, H]
    const float* w_gateup = (const float*)d_in[1];  // [H, 2I]
    const float* w_down   = (const float*)d_in[2];  // [I, H]
    float* out = (float*)d_out;                     // [T, H]

    float* x;
    cudaGetSymbolAddress((void**)&x, g_x);

    // Kernel 1: [T,H] @ [H,2I] fused SiLU*Mul -> x [T, I]
    {
        dim3 grid(I_DIM / 64, T_TOK / 128);
        gateup_silu_kernel<<<grid, 256>>>(hidden, w_gateup, x);
    }
    // Kernel 2: x [T,I] @ [I,H] -> out [T, H]
    {
        dim3 grid(H_DIM / 128, T_TOK / 128);
        down_kernel<<<grid, 256>>>(x, w_down, out);
    }
}